// round 4
// baseline (speedup 1.0000x reference)
#include <cuda_runtime.h>
#include <cstdint>

using ull = unsigned long long;
#define NROW 1024
#define NDIM 256
#define ROWS 8          // rows per CTA
#define ICH  32         // i-chunk per CTA
#define JG   8          // j-interleave groups (one per warp)

__device__ __forceinline__ void fma2(ull& d, ull a, ull b) {
    asm("fma.rn.f32x2 %0, %1, %2, %0;" : "+l"(d) : "l"(a), "l"(b));
}
__device__ __forceinline__ ull mul2(ull a, ull b) {
    ull r; asm("mul.rn.f32x2 %0, %1, %2;" : "=l"(r) : "l"(a), "l"(b));
    return r;
}
// suffix-parity mask: bit p of Uof(j) = parity of bits of j strictly above p.
// XOR-linear: Uof(a^b) = Uof(a)^Uof(b).
__host__ __device__ constexpr unsigned Uof(unsigned j) {
    unsigned v = j >> 1; v ^= v >> 1; v ^= v >> 2; v ^= v >> 4;
    return v & 255u;
}

// indicator words over m in [0,32): bit m set iff condition holds
__device__ __forceinline__ unsigned subsetWord(unsigned M) {   // m subset of M
    const unsigned magic[5] = {0xAAAAAAAAu, 0xCCCCCCCCu, 0xF0F0F0F0u,
                               0xFF00FF00u, 0xFFFF0000u};
    unsigned w = 0xFFFFFFFFu;
    #pragma unroll
    for (int b = 0; b < 5; ++b)
        if (!((M >> b) & 1u)) w &= ~magic[b];
    return w;
}
__device__ __forceinline__ unsigned supersetWord(unsigned M) { // m superset of M
    const unsigned magic[5] = {0xAAAAAAAAu, 0xCCCCCCCCu, 0xF0F0F0F0u,
                               0xFF00FF00u, 0xFFFF0000u};
    unsigned w = 0xFFFFFFFFu;
    #pragma unroll
    for (int b = 0; b < 5; ++b)
        if ((M >> b) & 1u) w &= magic[b];
    return w;
}

__global__ void __launch_bounds__(256, 5)
clifford_kernel(const float* __restrict__ A, const float* __restrict__ B,
                float* __restrict__ out) {
    // overlay reduction staging onto the tiles: 24KB total (was 40KB)
    __shared__ union SmemU {
        struct { float4 As[2][NDIM]; float4 Bs[2][NDIM]; } t;
        ull stage[12][JG][ICH];
    } sm;

    const unsigned tid = threadIdx.x;
    const unsigned gb  = blockIdx.x >> 3;   // row-group 0..127
    const unsigned ic  = blockIdx.x & 7;    // i-chunk   0..7
    const unsigned rowBase = gb * ROWS;
    const unsigned ibase   = ic * ICH;

    // ---- fill: thread tid stages component slot j = tid for all 8 rows ----
    {
        const unsigned j = tid;
        const float sg = (__popc(j & Uof(j)) & 1) ? -1.0f : 1.0f;
        float av[8], bv[8];
        #pragma unroll
        for (int r = 0; r < 8; ++r) {
            av[r] = A[(size_t)(rowBase + r) * NDIM + j] * sg;
            bv[r] = B[(size_t)(rowBase + r) * NDIM + j];
        }
        sm.t.As[0][j] = make_float4(av[0], av[1], av[2], av[3]);
        sm.t.As[1][j] = make_float4(av[4], av[5], av[6], av[7]);
        sm.t.Bs[0][j] = make_float4(bv[0], bv[1], bv[2], bv[3]);
        sm.t.Bs[1][j] = make_float4(bv[4], bv[5], bv[6], bv[7]);
    }
    __syncthreads();

    const unsigned il   = tid & 31;         // lane -> i within chunk
    const unsigned jg   = tid >> 5;         // warp -> j residue (mod 8)
    const unsigned i    = ibase + il;
    const unsigned Mh   = i >> 3;           // high 5 bits of i
    const unsigned ilow = i & 7u;

    // hoisted per-thread sign base (j = 8m | jg)
    const unsigned ph     = (unsigned)(__popc(i & Uof(jg)) & 1) << 31;
    const unsigned sgbase = 0x3f800000u ^ ph;   // ±1.0f base

    // predicate indicator words over m:
    //   wedge: j subset of i  <=>  jg subset of i_low  AND  m subset of Mh
    //   inner: (i&j)==0  OR  (i&j)==i
    //     t==0 <=> (i&jg)==0 AND m subset of ~Mh
    //     t==i <=> i subset of j <=> (ilow & ~jg)==0 AND m superset of Mh
    const unsigned Wwe  = ((jg & ~i & 7u) == 0u) ? subsetWord(Mh) : 0u;
    const unsigned Wdis = ((i & jg) == 0u)       ? subsetWord(~Mh & 31u) : 0u;
    const unsigned Wsup = ((ilow & ~jg) == 0u)   ? supersetWord(Mh) : 0u;
    const unsigned Winn = Wdis | Wsup;

    ull acc[12];                                 // [prod*4 + pair]
    #pragma unroll
    for (int q = 0; q < 12; ++q) acc[q] = 0ull;

    const ulonglong2* __restrict__ As0 = reinterpret_cast<const ulonglong2*>(&sm.t.As[0][0]);
    const ulonglong2* __restrict__ As1 = reinterpret_cast<const ulonglong2*>(&sm.t.As[1][0]);
    const ulonglong2* __restrict__ Bs0 = reinterpret_cast<const ulonglong2*>(&sm.t.Bs[0][0]);
    const ulonglong2* __restrict__ Bs1 = reinterpret_cast<const ulonglong2*>(&sm.t.Bs[1][0]);

    #pragma unroll
    for (unsigned m = 0; m < 32; ++m) {
        const unsigned jh = 8u * m;            // compile-time constant
        const unsigned cU = Uof(jh);           // compile-time constant
        const unsigned j  = jh | jg;
        const unsigned x  = i ^ j;

        // sign = parity(i & U_j): const-j part + hoisted part
        const unsigned pc = (unsigned)__popc(i & cU);
        const unsigned sg = sgbase ^ (pc << 31);          // float bits of ±1
        const ull sg2 = ((ull)sg << 32) | sg;

        const bool pw = (Wwe  >> m) & 1u;
        const bool pi = (Winn >> m) & 1u;

        const ulonglong2 a0 = As0[j];   // broadcast (warp-uniform j)
        const ulonglong2 a1 = As1[j];
        const ulonglong2 b0 = Bs0[x];   // conflict-free lane permutation
        const ulonglong2 b1 = Bs1[x];

        ull t0 = mul2(a0.x, b0.x);
        fma2(acc[0], t0, sg2); if (pw) fma2(acc[4], t0, sg2); if (pi) fma2(acc[8],  t0, sg2);
        ull t1 = mul2(a0.y, b0.y);
        fma2(acc[1], t1, sg2); if (pw) fma2(acc[5], t1, sg2); if (pi) fma2(acc[9],  t1, sg2);
        ull t2 = mul2(a1.x, b1.x);
        fma2(acc[2], t2, sg2); if (pw) fma2(acc[6], t2, sg2); if (pi) fma2(acc[10], t2, sg2);
        ull t3 = mul2(a1.y, b1.y);
        fma2(acc[3], t3, sg2); if (pw) fma2(acc[7], t3, sg2); if (pi) fma2(acc[11], t3, sg2);
    }

    // ---- deterministic cross-warp reduction over the 8 j-groups ----
    __syncthreads();                 // all warps done reading tiles before overwrite
    #pragma unroll
    for (int q = 0; q < 12; ++q)
        sm.stage[q][jg][il] = acc[q];
    __syncthreads();

    {
        const unsigned qh0 = (tid >> 5) * 3;        // 3 outputs per thread
        #pragma unroll
        for (int k = 0; k < 3; ++k) {
            const unsigned qh   = qh0 + k;          // 0..23 = prod*8 + row
            const unsigned prod = qh >> 3;
            const unsigned r    = qh & 7;
            const unsigned pair = r >> 1;
            const unsigned hf   = r & 1;
            const float* sp = reinterpret_cast<const float*>(&sm.stage[prod * 4 + pair][0][0]);
            float s = 0.0f;
            #pragma unroll
            for (int w = 0; w < 8; ++w)
                s += sp[(w * ICH + il) * 2 + hf];
            out[(size_t)prod * (NROW * NDIM) + (size_t)(rowBase + r) * NDIM + ibase + il] = s;
        }
    }
}

extern "C" void kernel_launch(void* const* d_in, const int* in_sizes, int n_in,
                              void* d_out, int out_size) {
    const float* A = (const float*)d_in[0];
    const float* B = (const float*)d_in[1];
    float* out = (float*)d_out;
    // 1024 rows / 8 rows-per-CTA = 128 row-groups; x 8 i-chunks = 1024 CTAs
    clifford_kernel<<<1024, 256>>>(A, B, out);
}